// round 7
// baseline (speedup 1.0000x reference)
#include <cuda_runtime.h>
#include <cuda_fp16.h>
#include <cstdint>

#define Bv 256
#define Tv 150
#define Fv 1024
#define Uv 28
#define G3 84   // 3*U

#define LOG2E  1.4426950408889634f

// ---------------- scratch (device globals; no allocation allowed) ----------
__device__ __half g_C[(size_t)Bv * Tv * Fv];   // UaH + biases, fp16 (78.6 MB)
__device__ __half g_XG[(size_t)Bv * Tv * G3];  // x @ gru_kernel, fp16 (6.4 MB)
__device__ __half g_WaS[Bv * Fv];              // h@Wa, fp16 (0.5 MB)
__device__ float  g_scores[Bv * Tv];
__device__ float  g_h[Bv * Uv];

// ---------------- fast-math helpers ----------------------------------------
__device__ __forceinline__ float ex2f(float x) {
    float y; asm("ex2.approx.ftz.f32 %0, %1;" : "=f"(y) : "f"(x)); return y;
}
__device__ __forceinline__ float rcpf(float x) {
    float y; asm("rcp.approx.ftz.f32 %0, %1;" : "=f"(y) : "f"(x)); return y;
}
__device__ __forceinline__ float tanh_hw(float x) {
    float y; asm("tanh.approx.f32 %0, %1;" : "=f"(y) : "f"(x)); return y;
}
__device__ __forceinline__ float tanh_acc(float a) {
    float e = ex2f(a * (2.0f * LOG2E));
    return fmaf(-2.0f, rcpf(e + 1.0f), 1.0f);
}
__device__ __forceinline__ float sigmoid_fast(float a) {
    float e = ex2f(-a * LOG2E);
    return rcpf(1.0f + e);
}

// ---------------- init ------------------------------------------------------
__global__ void init_kernel() {
    int i = blockIdx.x * blockDim.x + threadIdx.x;
    if (i < Bv * Fv) g_WaS[i] = __float2half(0.0f);
    if (i < Bv * Uv) g_h[i] = 0.0f;
}

// ---------------- tensor-core GEMM: fp32 in (converted to fp16), fp32 acc --
#define BM 128
#define BN 128
#define BKg 16
#define PITCH 24

__device__ __forceinline__ void mma16816(float* d,
    uint32_t a0, uint32_t a1, uint32_t a2, uint32_t a3,
    uint32_t b0, uint32_t b1)
{
    asm volatile(
        "mma.sync.aligned.m16n8k16.row.col.f32.f16.f16.f32 "
        "{%0,%1,%2,%3}, {%4,%5,%6,%7}, {%8,%9}, {%0,%1,%2,%3};"
        : "+f"(d[0]), "+f"(d[1]), "+f"(d[2]), "+f"(d[3])
        : "r"(a0), "r"(a1), "r"(a2), "r"(a3), "r"(b0), "r"(b1));
}

__global__ __launch_bounds__(256)
void gemm_mma(const float* __restrict__ A, int lda,
              const float* __restrict__ Bm, int ldb,
              __half* __restrict__ Cm, int ldc, int Ncols,
              const float* __restrict__ bias1,
              const float* __restrict__ bias2)
{
    __shared__ __align__(16) __half As[BM * PITCH];   // [m][k]
    __shared__ __align__(16) __half Bs[BN * PITCH];   // [n][k]

    int tid = threadIdx.x, lane = tid & 31, wid = tid >> 5;
    int warp_m = wid & 3, warp_n = wid >> 2;
    int bm = blockIdx.y * BM, bn = blockIdx.x * BN;
    int g = lane >> 2, tg = lane & 3;

    int a_row[2], a_kq[2], b_n[2], b_kq[2];
#pragma unroll
    for (int i = 0; i < 2; i++) {
        int fa = tid + 256 * i;
        a_row[i] = fa >> 2; a_kq[i] = fa & 3;
        b_n[i] = fa & 127;  b_kq[i] = fa >> 7;
    }

    float4 pa[2];
    float  pb[2][4];
#pragma unroll
    for (int i = 0; i < 2; i++) {
        pa[i] = *(const float4*)&A[(size_t)(bm + a_row[i]) * lda + a_kq[i] * 4];
        int col = bn + b_n[i];
        bool ok = col < Ncols;
#pragma unroll
        for (int j = 0; j < 4; j++)
            pb[i][j] = ok ? Bm[(size_t)(b_kq[i] * 4 + j) * ldb + col] : 0.0f;
    }

    float acc[2][8][4];
#pragma unroll
    for (int t = 0; t < 2; t++)
#pragma unroll
        for (int j = 0; j < 8; j++)
#pragma unroll
            for (int q = 0; q < 4; q++) acc[t][j][q] = 0.0f;

    const int KT = Fv / BKg;
    for (int kt = 0; kt < KT; kt++) {
        __syncthreads();
#pragma unroll
        for (int i = 0; i < 2; i++) {
            __half2 h0 = __floats2half2_rn(pa[i].x, pa[i].y);
            __half2 h1 = __floats2half2_rn(pa[i].z, pa[i].w);
            *(__half2*)&As[a_row[i] * PITCH + a_kq[i] * 4]     = h0;
            *(__half2*)&As[a_row[i] * PITCH + a_kq[i] * 4 + 2] = h1;
            __half2 g0 = __floats2half2_rn(pb[i][0], pb[i][1]);
            __half2 g1 = __floats2half2_rn(pb[i][2], pb[i][3]);
            *(__half2*)&Bs[b_n[i] * PITCH + b_kq[i] * 4]     = g0;
            *(__half2*)&Bs[b_n[i] * PITCH + b_kq[i] * 4 + 2] = g1;
        }
        if (kt + 1 < KT) {
            int k0 = (kt + 1) * BKg;
#pragma unroll
            for (int i = 0; i < 2; i++) {
                pa[i] = *(const float4*)&A[(size_t)(bm + a_row[i]) * lda + k0 + a_kq[i] * 4];
                int col = bn + b_n[i];
                bool ok = col < Ncols;
#pragma unroll
                for (int j = 0; j < 4; j++)
                    pb[i][j] = ok ? Bm[(size_t)(k0 + b_kq[i] * 4 + j) * ldb + col] : 0.0f;
            }
        }
        __syncthreads();

        uint32_t af[2][4];
#pragma unroll
        for (int t = 0; t < 2; t++) {
            int m = warp_m * 32 + t * 16 + g;
            af[t][0] = *(const uint32_t*)&As[m * PITCH + tg * 2];
            af[t][1] = *(const uint32_t*)&As[(m + 8) * PITCH + tg * 2];
            af[t][2] = *(const uint32_t*)&As[m * PITCH + tg * 2 + 8];
            af[t][3] = *(const uint32_t*)&As[(m + 8) * PITCH + tg * 2 + 8];
        }
#pragma unroll
        for (int j = 0; j < 8; j++) {
            int n = warp_n * 64 + j * 8 + g;
            uint32_t b0 = *(const uint32_t*)&Bs[n * PITCH + tg * 2];
            uint32_t b1 = *(const uint32_t*)&Bs[n * PITCH + tg * 2 + 8];
#pragma unroll
            for (int t = 0; t < 2; t++)
                mma16816(acc[t][j], af[t][0], af[t][1], af[t][2], af[t][3], b0, b1);
        }
    }

#pragma unroll
    for (int t = 0; t < 2; t++) {
        int row = bm + warp_m * 32 + t * 16 + g;
#pragma unroll
        for (int j = 0; j < 8; j++) {
            int col = bn + warp_n * 64 + j * 8 + tg * 2;
            if (col < Ncols) {
                float bb0 = 0.f, bb1 = 0.f;
                if (bias1) {
                    bb0 = bias1[col] + bias2[col];
                    bb1 = bias1[col + 1] + bias2[col + 1];
                }
                __half2 lo = __floats2half2_rn(acc[t][j][0] + bb0, acc[t][j][1] + bb1);
                __half2 hi = __floats2half2_rn(acc[t][j][2] + bb0, acc[t][j][3] + bb1);
                *(__half2*)&Cm[(size_t)row * ldc + col]       = lo;
                *(__half2*)&Cm[(size_t)(row + 8) * ldc + col] = hi;
            }
        }
    }
}

// ---------------- per-step score kernel ------------------------------------
// warp per (b,t): score = sum_f tanh(C + WaS) * Va.
// R1-shaped: simple interleaved loop, low registers, HIGH OCCUPANCY (the
// measured bandwidth lever: R1 @occ89% hit 5.5TB/s; batched variants @occ43%
// were stuck at 3.7TB/s). Va cached in smem per block (kills 4KB/row global
// re-reads); C streams; WaS is L1/L2-hot.
__global__ __launch_bounds__(256, 7)
void score_kernel(const float* __restrict__ Va)
{
    __shared__ float sVa[Fv];   // 4 KB
    ((float4*)sVa)[threadIdx.x] = ((const float4*)Va)[threadIdx.x]; // 256*16B
    __syncthreads();

    int warp = threadIdx.x >> 5, lane = threadIdx.x & 31;
    int row = blockIdx.x * 8 + warp;          // < B*T = 38400
    int b = row / Tv;

    const uint4* C4 = (const uint4*)(g_C + (size_t)row * Fv);   // 64 x 16B
    const uint4* W4 = (const uint4*)(g_WaS + (size_t)b * Fv);

    float a0 = 0.f, a1 = 0.f, a2 = 0.f, a3 = 0.f;
#pragma unroll
    for (int i = 0; i < 4; i++) {
        int idx = i * 32 + lane;              // 16B chunk index (8 halves)
        uint4 c = __ldg(&C4[idx]);
        uint4 w = __ldg(&W4[idx]);
        const float4 v0 = *(const float4*)&sVa[idx * 8];
        const float4 v1 = *(const float4*)&sVa[idx * 8 + 4];
        const __half2* ch = (const __half2*)&c;
        const __half2* wh = (const __half2*)&w;

        float2 s0 = __half22float2(__hadd2(ch[0], wh[0]));
        float2 s1 = __half22float2(__hadd2(ch[1], wh[1]));
        float2 s2 = __half22float2(__hadd2(ch[2], wh[2]));
        float2 s3 = __half22float2(__hadd2(ch[3], wh[3]));

        a0 = fmaf(tanh_hw(s0.x), v0.x, a0);
        a1 = fmaf(tanh_hw(s0.y), v0.y, a1);
        a2 = fmaf(tanh_hw(s1.x), v0.z, a2);
        a3 = fmaf(tanh_hw(s1.y), v0.w, a3);
        a0 = fmaf(tanh_hw(s2.x), v1.x, a0);
        a1 = fmaf(tanh_hw(s2.y), v1.y, a1);
        a2 = fmaf(tanh_hw(s3.x), v1.z, a2);
        a3 = fmaf(tanh_hw(s3.y), v1.w, a3);
    }
    float sum = (a0 + a1) + (a2 + a3);
#pragma unroll
    for (int off = 16; off > 0; off >>= 1)
        sum += __shfl_xor_sync(0xffffffffu, sum, off);
    if (lane == 0) g_scores[row] = sum;
}

// ---------------- per-step softmax + GRU + next WaS (1 block per batch b) --
__global__ __launch_bounds__(256)
void att_gru_kernel(const float* __restrict__ Wa,
                    const float* __restrict__ grk,
                    const float* __restrict__ gb,
                    float* __restrict__ out, int tstep)
{
    int b = blockIdx.x, tid = threadIdx.x;

    __shared__ float sa[Tv];
    __shared__ float red[256];
    __shared__ float spart[3 * G3];
    __shared__ float sxz[G3], shz[G3];
    __shared__ float sh[Uv], shnew[Uv];

    if (tid < Uv) sh[tid] = g_h[b * Uv + tid];

    // ---- softmax over T=150 scores ----
    float v = (tid < Tv) ? g_scores[b * Tv + tid] : -1e30f;
    red[tid] = v;
    __syncthreads();
#pragma unroll
    for (int s = 128; s > 0; s >>= 1) {
        if (tid < s) red[tid] = fmaxf(red[tid], red[tid + s]);
        __syncthreads();
    }
    float mx = red[0];
    __syncthreads();
    float e = 0.0f;
    if (tid < Tv) e = ex2f((v - mx) * LOG2E);
    red[tid] = e;
    __syncthreads();
#pragma unroll
    for (int s = 128; s > 0; s >>= 1) {
        if (tid < s) red[tid] += red[tid + s];
        __syncthreads();
    }
    float inv = rcpf(red[0]);
    if (tid < Tv) sa[tid] = e * inv;
    __syncthreads();

    // ---- xz[j] = bias0[j] + sum_t a[t] * XG[b,t,j] ----
    int part = tid / G3;        // 0..2 used; tid>=252 idle
    int j = tid - part * G3;
    if (part < 3) {
        float acc = 0.0f;
        const __half* XGb = g_XG + (size_t)b * Tv * G3 + j;
        for (int t = part; t < Tv; t += 3)
            acc = fmaf(sa[t], __half2float(XGb[t * G3]), acc);
        spart[part * G3 + j] = acc;
    }
    __syncthreads();

    if (tid < G3) {
        float xz = gb[tid] + spart[tid] + spart[G3 + tid] + spart[2 * G3 + tid];
        float hzv = gb[G3 + tid];
#pragma unroll
        for (int u = 0; u < Uv; u++)
            hzv = fmaf(sh[u], grk[u * G3 + tid], hzv);
        sxz[tid] = xz;
        shz[tid] = hzv;
    }
    __syncthreads();

    // ---- GRU gates (reset_after=True) ----
    if (tid < Uv) {
        float z  = sigmoid_fast(sxz[tid]          + shz[tid]);
        float r  = sigmoid_fast(sxz[Uv + tid]     + shz[Uv + tid]);
        float hh = tanh_acc    (sxz[2 * Uv + tid] + r * shz[2 * Uv + tid]);
        float hn = hh + z * (sh[tid] - hh);
        g_h[b * Uv + tid] = hn;
        out[((size_t)b * Tv + tstep) * Uv + tid] = hn;
        shnew[tid] = hn;
    }
    __syncthreads();

    // ---- WaS for next step: h_new @ Wa (stored fp16) ----
    float4 w = make_float4(0.f, 0.f, 0.f, 0.f);
    const float4* Wa4 = (const float4*)Wa;
#pragma unroll
    for (int u = 0; u < Uv; u++) {
        float hv = shnew[u];
        float4 wv = Wa4[u * (Fv / 4) + tid];
        w.x = fmaf(hv, wv.x, w.x);
        w.y = fmaf(hv, wv.y, w.y);
        w.z = fmaf(hv, wv.z, w.z);
        w.w = fmaf(hv, wv.w, w.w);
    }
    __half2 p0 = __floats2half2_rn(w.x, w.y);
    __half2 p1 = __floats2half2_rn(w.z, w.w);
    uint2 pk;
    pk.x = *(uint32_t*)&p0;
    pk.y = *(uint32_t*)&p1;
    ((uint2*)g_WaS)[b * (Fv / 4) + tid] = pk;
}

// ---------------- launch -----------------------------------------------------
extern "C" void kernel_launch(void* const* d_in, const int* in_sizes, int n_in,
                              void* d_out, int out_size)
{
    const float* x   = (const float*)d_in[0];  // (B,T,F)
    const float* Wa  = (const float*)d_in[1];  // (U,F)
    const float* Ua  = (const float*)d_in[2];  // (F,F)
    const float* Va  = (const float*)d_in[3];  // (F,1)
    const float* Ba1 = (const float*)d_in[4];  // (1,F)
    const float* Ba2 = (const float*)d_in[5];  // (1,F)
    // d_in[6] = Ba3 : softmax-invariant, unused
    const float* gk  = (const float*)d_in[7];  // (F,3U)
    const float* grk = (const float*)d_in[8];  // (U,3U)
    const float* gb  = (const float*)d_in[9];  // (2,3U)
    float* out = (float*)d_out;                // (B,T,U)

    init_kernel<<<(Bv * Fv + 255) / 256, 256>>>();

    __half* Cm;  cudaGetSymbolAddress((void**)&Cm, g_C);
    __half* XGm; cudaGetSymbolAddress((void**)&XGm, g_XG);

    // C = x @ Ua + Ba1 + Ba2  : M=38400, N=1024, K=1024  (fp16 out, HMMA)
    gemm_mma<<<dim3(Fv / BN, (Bv * Tv) / BM), 256>>>(
        x, Fv, Ua, Fv, Cm, Fv, Fv, Ba1, Ba2);
    // XG = x @ gru_kernel     : M=38400, N=84, K=1024    (fp16 out, HMMA)
    gemm_mma<<<dim3(1, (Bv * Tv) / BM), 256>>>(
        x, Fv, gk, G3, XGm, G3, G3, nullptr, nullptr);

    for (int t = 0; t < Tv; t++) {
        score_kernel<<<(Bv * Tv) / 8, 256>>>(Va);
        att_gru_kernel<<<Bv, 256>>>(Wa, grk, gb, out, t);
    }
}

// round 8
// speedup vs baseline: 1.1705x; 1.1705x over previous
#include <cuda_runtime.h>
#include <cuda_fp16.h>
#include <cstdint>

#define Bv 256
#define Tv 150
#define Fv 1024
#define Uv 28
#define G3 84   // 3*U
#define TCH 30  // t-rows per score block (5 chunks cover T=150)

#define LOG2E  1.4426950408889634f

// ---------------- scratch (device globals; no allocation allowed) ----------
__device__ __half g_C[(size_t)Bv * Tv * Fv];   // UaH + biases, fp16 (78.6 MB)
__device__ __half g_XG[(size_t)Bv * Tv * G3];  // x @ gru_kernel, fp16 (6.4 MB)
__device__ __half g_WaS[Bv * Fv];              // h@Wa, fp16 (0.5 MB)
__device__ float  g_scores[Bv * Tv];
__device__ float  g_h[Bv * Uv];

// ---------------- fast-math helpers ----------------------------------------
__device__ __forceinline__ float ex2f(float x) {
    float y; asm("ex2.approx.ftz.f32 %0, %1;" : "=f"(y) : "f"(x)); return y;
}
__device__ __forceinline__ float rcpf(float x) {
    float y; asm("rcp.approx.ftz.f32 %0, %1;" : "=f"(y) : "f"(x)); return y;
}
__device__ __forceinline__ float tanh_hw(float x) {
    float y; asm("tanh.approx.f32 %0, %1;" : "=f"(y) : "f"(x)); return y;
}
__device__ __forceinline__ float tanh_acc(float a) {
    float e = ex2f(a * (2.0f * LOG2E));
    return fmaf(-2.0f, rcpf(e + 1.0f), 1.0f);
}
__device__ __forceinline__ float sigmoid_fast(float a) {
    float e = ex2f(-a * LOG2E);
    return rcpf(1.0f + e);
}

// ---------------- init ------------------------------------------------------
__global__ void init_kernel() {
    int i = blockIdx.x * blockDim.x + threadIdx.x;
    if (i < Bv * Fv) g_WaS[i] = __float2half(0.0f);
    if (i < Bv * Uv) g_h[i] = 0.0f;
}

// ---------------- tensor-core GEMM: fp32 in (converted to fp16), fp32 acc --
#define BM 128
#define BN 128
#define BKg 16
#define PITCH 24

__device__ __forceinline__ void mma16816(float* d,
    uint32_t a0, uint32_t a1, uint32_t a2, uint32_t a3,
    uint32_t b0, uint32_t b1)
{
    asm volatile(
        "mma.sync.aligned.m16n8k16.row.col.f32.f16.f16.f32 "
        "{%0,%1,%2,%3}, {%4,%5,%6,%7}, {%8,%9}, {%0,%1,%2,%3};"
        : "+f"(d[0]), "+f"(d[1]), "+f"(d[2]), "+f"(d[3])
        : "r"(a0), "r"(a1), "r"(a2), "r"(a3), "r"(b0), "r"(b1));
}

__global__ __launch_bounds__(256)
void gemm_mma(const float* __restrict__ A, int lda,
              const float* __restrict__ Bm, int ldb,
              __half* __restrict__ Cm, int ldc, int Ncols,
              const float* __restrict__ bias1,
              const float* __restrict__ bias2)
{
    __shared__ __align__(16) __half As[BM * PITCH];   // [m][k]
    __shared__ __align__(16) __half Bs[BN * PITCH];   // [n][k]

    int tid = threadIdx.x, lane = tid & 31, wid = tid >> 5;
    int warp_m = wid & 3, warp_n = wid >> 2;
    int bm = blockIdx.y * BM, bn = blockIdx.x * BN;
    int g = lane >> 2, tg = lane & 3;

    int a_row[2], a_kq[2], b_n[2], b_kq[2];
#pragma unroll
    for (int i = 0; i < 2; i++) {
        int fa = tid + 256 * i;
        a_row[i] = fa >> 2; a_kq[i] = fa & 3;
        b_n[i] = fa & 127;  b_kq[i] = fa >> 7;
    }

    float4 pa[2];
    float  pb[2][4];
#pragma unroll
    for (int i = 0; i < 2; i++) {
        pa[i] = *(const float4*)&A[(size_t)(bm + a_row[i]) * lda + a_kq[i] * 4];
        int col = bn + b_n[i];
        bool ok = col < Ncols;
#pragma unroll
        for (int j = 0; j < 4; j++)
            pb[i][j] = ok ? Bm[(size_t)(b_kq[i] * 4 + j) * ldb + col] : 0.0f;
    }

    float acc[2][8][4];
#pragma unroll
    for (int t = 0; t < 2; t++)
#pragma unroll
        for (int j = 0; j < 8; j++)
#pragma unroll
            for (int q = 0; q < 4; q++) acc[t][j][q] = 0.0f;

    const int KT = Fv / BKg;
    for (int kt = 0; kt < KT; kt++) {
        __syncthreads();
#pragma unroll
        for (int i = 0; i < 2; i++) {
            __half2 h0 = __floats2half2_rn(pa[i].x, pa[i].y);
            __half2 h1 = __floats2half2_rn(pa[i].z, pa[i].w);
            *(__half2*)&As[a_row[i] * PITCH + a_kq[i] * 4]     = h0;
            *(__half2*)&As[a_row[i] * PITCH + a_kq[i] * 4 + 2] = h1;
            __half2 g0 = __floats2half2_rn(pb[i][0], pb[i][1]);
            __half2 g1 = __floats2half2_rn(pb[i][2], pb[i][3]);
            *(__half2*)&Bs[b_n[i] * PITCH + b_kq[i] * 4]     = g0;
            *(__half2*)&Bs[b_n[i] * PITCH + b_kq[i] * 4 + 2] = g1;
        }
        if (kt + 1 < KT) {
            int k0 = (kt + 1) * BKg;
#pragma unroll
            for (int i = 0; i < 2; i++) {
                pa[i] = *(const float4*)&A[(size_t)(bm + a_row[i]) * lda + k0 + a_kq[i] * 4];
                int col = bn + b_n[i];
                bool ok = col < Ncols;
#pragma unroll
                for (int j = 0; j < 4; j++)
                    pb[i][j] = ok ? Bm[(size_t)(k0 + b_kq[i] * 4 + j) * ldb + col] : 0.0f;
            }
        }
        __syncthreads();

        uint32_t af[2][4];
#pragma unroll
        for (int t = 0; t < 2; t++) {
            int m = warp_m * 32 + t * 16 + g;
            af[t][0] = *(const uint32_t*)&As[m * PITCH + tg * 2];
            af[t][1] = *(const uint32_t*)&As[(m + 8) * PITCH + tg * 2];
            af[t][2] = *(const uint32_t*)&As[m * PITCH + tg * 2 + 8];
            af[t][3] = *(const uint32_t*)&As[(m + 8) * PITCH + tg * 2 + 8];
        }
#pragma unroll
        for (int j = 0; j < 8; j++) {
            int n = warp_n * 64 + j * 8 + g;
            uint32_t b0 = *(const uint32_t*)&Bs[n * PITCH + tg * 2];
            uint32_t b1 = *(const uint32_t*)&Bs[n * PITCH + tg * 2 + 8];
#pragma unroll
            for (int t = 0; t < 2; t++)
                mma16816(acc[t][j], af[t][0], af[t][1], af[t][2], af[t][3], b0, b1);
        }
    }

#pragma unroll
    for (int t = 0; t < 2; t++) {
        int row = bm + warp_m * 32 + t * 16 + g;
#pragma unroll
        for (int j = 0; j < 8; j++) {
            int col = bn + warp_n * 64 + j * 8 + tg * 2;
            if (col < Ncols) {
                float bb0 = 0.f, bb1 = 0.f;
                if (bias1) {
                    bb0 = bias1[col] + bias2[col];
                    bb1 = bias1[col + 1] + bias2[col + 1];
                }
                __half2 lo = __floats2half2_rn(acc[t][j][0] + bb0, acc[t][j][1] + bb1);
                __half2 hi = __floats2half2_rn(acc[t][j][2] + bb0, acc[t][j][3] + bb1);
                *(__half2*)&Cm[(size_t)row * ldc + col]       = lo;
                *(__half2*)&Cm[(size_t)(row + 8) * ldc + col] = hi;
            }
        }
    }
}

// ---------------- per-step score kernel ------------------------------------
// Block = (b, chunk of 30 t's). WaS[b] + Va staged in smem ONCE per block;
// each warp walks ~4 rows with explicit next-row prefetch so the DRAM wait
// of row t+8 overlaps the tanh/FFMA body of row t (cross-row pipelining —
// the per-row serial-round structure was the measured R1..R7 bottleneck).
__global__ __launch_bounds__(256)
void score_kernel(const float* __restrict__ Va)
{
    __shared__ float  sVa[Fv];      // 4 KB
    __shared__ __half sW[Fv];       // 2 KB

    int b = blockIdx.y;
    int t0 = blockIdx.x * TCH;
    int tid = threadIdx.x, warp = tid >> 5, lane = tid & 31;

    ((float4*)sVa)[tid] = ((const float4*)Va)[tid];            // 256 x 16B
    if (tid < 128)
        ((uint4*)sW)[tid] = ((const uint4*)(g_WaS + (size_t)b * Fv))[tid];
    __syncthreads();

    int tEnd = t0 + TCH; if (tEnd > Tv) tEnd = Tv;
    int t = t0 + warp;
    if (t >= tEnd) return;

    const uint4* Cb = (const uint4*)(g_C + (size_t)b * Tv * Fv);  // 128 chunks/row

    uint4 cur[4];
#pragma unroll
    for (int i = 0; i < 4; i++)
        cur[i] = __ldg(Cb + (size_t)t * 128 + i * 32 + lane);

    while (t < tEnd) {
        int tn = t + 8;
        int tl = (tn < tEnd) ? tn : t;        // clamp: prefetch valid memory
        uint4 nxt[4];
#pragma unroll
        for (int i = 0; i < 4; i++)
            nxt[i] = __ldg(Cb + (size_t)tl * 128 + i * 32 + lane);

        float a0 = 0.f, a1 = 0.f, a2 = 0.f, a3 = 0.f;
#pragma unroll
        for (int i = 0; i < 4; i++) {
            int idx = i * 32 + lane;
            uint4 w = *(const uint4*)&sW[idx * 8];
            float4 v0 = *(const float4*)&sVa[idx * 8];
            float4 v1 = *(const float4*)&sVa[idx * 8 + 4];
            const __half2* ch = (const __half2*)&cur[i];
            const __half2* wh = (const __half2*)&w;

            float2 s0 = __half22float2(__hadd2(ch[0], wh[0]));
            float2 s1 = __half22float2(__hadd2(ch[1], wh[1]));
            float2 s2 = __half22float2(__hadd2(ch[2], wh[2]));
            float2 s3 = __half22float2(__hadd2(ch[3], wh[3]));

            a0 = fmaf(tanh_hw(s0.x), v0.x, a0);
            a1 = fmaf(tanh_hw(s0.y), v0.y, a1);
            a2 = fmaf(tanh_hw(s1.x), v0.z, a2);
            a3 = fmaf(tanh_hw(s1.y), v0.w, a3);
            a0 = fmaf(tanh_hw(s2.x), v1.x, a0);
            a1 = fmaf(tanh_hw(s2.y), v1.y, a1);
            a2 = fmaf(tanh_hw(s3.x), v1.z, a2);
            a3 = fmaf(tanh_hw(s3.y), v1.w, a3);
        }
        float sum = (a0 + a1) + (a2 + a3);
#pragma unroll
        for (int off = 16; off > 0; off >>= 1)
            sum += __shfl_xor_sync(0xffffffffu, sum, off);
        if (lane == 0) g_scores[b * Tv + t] = sum;

#pragma unroll
        for (int i = 0; i < 4; i++) cur[i] = nxt[i];
        t = tn;
    }
}

// ---------------- per-step softmax + GRU + next WaS (1 block per batch b) --
__global__ __launch_bounds__(256)
void att_gru_kernel(const float* __restrict__ Wa,
                    const float* __restrict__ grk,
                    const float* __restrict__ gb,
                    float* __restrict__ out, int tstep)
{
    int b = blockIdx.x, tid = threadIdx.x;

    __shared__ float sa[Tv];
    __shared__ float red[256];
    __shared__ float spart[3 * G3];
    __shared__ float sxz[G3], shz[G3];
    __shared__ float sh[Uv], shnew[Uv];

    if (tid < Uv) sh[tid] = g_h[b * Uv + tid];

    // ---- softmax over T=150 scores ----
    float v = (tid < Tv) ? g_scores[b * Tv + tid] : -1e30f;
    red[tid] = v;
    __syncthreads();
#pragma unroll
    for (int s = 128; s > 0; s >>= 1) {
        if (tid < s) red[tid] = fmaxf(red[tid], red[tid + s]);
        __syncthreads();
    }
    float mx = red[0];
    __syncthreads();
    float e = 0.0f;
    if (tid < Tv) e = ex2f((v - mx) * LOG2E);
    red[tid] = e;
    __syncthreads();
#pragma unroll
    for (int s = 128; s > 0; s >>= 1) {
        if (tid < s) red[tid] += red[tid + s];
        __syncthreads();
    }
    float inv = rcpf(red[0]);
    if (tid < Tv) sa[tid] = e * inv;
    __syncthreads();

    // ---- xz[j] = bias0[j] + sum_t a[t] * XG[b,t,j] ----
    int part = tid / G3;        // 0..2 used; tid>=252 idle
    int j = tid - part * G3;
    if (part < 3) {
        float acc = 0.0f;
        const __half* XGb = g_XG + (size_t)b * Tv * G3 + j;
        for (int t = part; t < Tv; t += 3)
            acc = fmaf(sa[t], __half2float(XGb[t * G3]), acc);
        spart[part * G3 + j] = acc;
    }
    __syncthreads();

    if (tid < G3) {
        float xz = gb[tid] + spart[tid] + spart[G3 + tid] + spart[2 * G3 + tid];
        float hzv = gb[G3 + tid];
#pragma unroll
        for (int u = 0; u < Uv; u++)
            hzv = fmaf(sh[u], grk[u * G3 + tid], hzv);
        sxz[tid] = xz;
        shz[tid] = hzv;
    }
    __syncthreads();

    // ---- GRU gates (reset_after=True) ----
    if (tid < Uv) {
        float z  = sigmoid_fast(sxz[tid]          + shz[tid]);
        float r  = sigmoid_fast(sxz[Uv + tid]     + shz[Uv + tid]);
        float hh = tanh_acc    (sxz[2 * Uv + tid] + r * shz[2 * Uv + tid]);
        float hn = hh + z * (sh[tid] - hh);
        g_h[b * Uv + tid] = hn;
        out[((size_t)b * Tv + tstep) * Uv + tid] = hn;
        shnew[tid] = hn;
    }
    __syncthreads();

    // ---- WaS for next step: h_new @ Wa (stored fp16) ----
    float4 w = make_float4(0.f, 0.f, 0.f, 0.f);
    const float4* Wa4 = (const float4*)Wa;
#pragma unroll
    for (int u = 0; u < Uv; u++) {
        float hv = shnew[u];
        float4 wv = Wa4[u * (Fv / 4) + tid];
        w.x = fmaf(hv, wv.x, w.x);
        w.y = fmaf(hv, wv.y, w.y);
        w.z = fmaf(hv, wv.z, w.z);
        w.w = fmaf(hv, wv.w, w.w);
    }
    __half2 p0 = __floats2half2_rn(w.x, w.y);
    __half2 p1 = __floats2half2_rn(w.z, w.w);
    uint2 pk;
    pk.x = *(uint32_t*)&p0;
    pk.y = *(uint32_t*)&p1;
    ((uint2*)g_WaS)[b * (Fv / 4) + tid] = pk;
}

// ---------------- launch -----------------------------------------------------
extern "C" void kernel_launch(void* const* d_in, const int* in_sizes, int n_in,
                              void* d_out, int out_size)
{
    const float* x   = (const float*)d_in[0];  // (B,T,F)
    const float* Wa  = (const float*)d_in[1];  // (U,F)
    const float* Ua  = (const float*)d_in[2];  // (F,F)
    const float* Va  = (const float*)d_in[3];  // (F,1)
    const float* Ba1 = (const float*)d_in[4];  // (1,F)
    const float* Ba2 = (const float*)d_in[5];  // (1,F)
    // d_in[6] = Ba3 : softmax-invariant, unused
    const float* gk  = (const float*)d_in[7];  // (F,3U)
    const float* grk = (const float*)d_in[8];  // (U,3U)
    const float* gb  = (const float*)d_in[9];  // (2,3U)
    float* out = (float*)d_out;                // (B,T,U)

    init_kernel<<<(Bv * Fv + 255) / 256, 256>>>();

    __half* Cm;  cudaGetSymbolAddress((void**)&Cm, g_C);
    __half* XGm; cudaGetSymbolAddress((void**)&XGm, g_XG);

    // C = x @ Ua + Ba1 + Ba2  : M=38400, N=1024, K=1024  (fp16 out, HMMA)
    gemm_mma<<<dim3(Fv / BN, (Bv * Tv) / BM), 256>>>(
        x, Fv, Ua, Fv, Cm, Fv, Fv, Ba1, Ba2);
    // XG = x @ gru_kernel     : M=38400, N=84, K=1024    (fp16 out, HMMA)
    gemm_mma<<<dim3(1, (Bv * Tv) / BM), 256>>>(
        x, Fv, gk, G3, XGm, G3, G3, nullptr, nullptr);

    dim3 sgrid((Tv + TCH - 1) / TCH, Bv);   // (5, 256)
    for (int t = 0; t < Tv; t++) {
        score_kernel<<<sgrid, 256>>>(Va);
        att_gru_kernel<<<Bv, 256>>>(Wa, grk, gb, out, t);
    }
}

// round 9
// speedup vs baseline: 1.2010x; 1.0261x over previous
#include <cuda_runtime.h>
#include <cuda_fp16.h>
#include <cstdint>

#define Bv 256
#define Tv 150
#define Fv 1024
#define Uv 28
#define G3 84   // 3*U
#define TCH 30  // t-rows per score block (5 chunks cover T=150)

#define LOG2E  1.4426950408889634f

// ---------------- scratch (device globals; no allocation allowed) ----------
__device__ __half g_C[(size_t)Bv * Tv * Fv];   // UaH + biases, fp16 (78.6 MB)
__device__ __half g_XG[(size_t)Bv * Tv * G3];  // x @ gru_kernel, fp16 (6.4 MB)
__device__ __half g_WaS[Bv * Fv];              // h@Wa, fp16 (0.5 MB)
__device__ float  g_scores[Bv * Tv];
__device__ float  g_h[Bv * Uv];

// ---------------- fast-math helpers ----------------------------------------
__device__ __forceinline__ float ex2f(float x) {
    float y; asm("ex2.approx.ftz.f32 %0, %1;" : "=f"(y) : "f"(x)); return y;
}
__device__ __forceinline__ float rcpf(float x) {
    float y; asm("rcp.approx.ftz.f32 %0, %1;" : "=f"(y) : "f"(x)); return y;
}
// 2-wide fp16 hardware tanh: HALVES the MUFU instruction count (the pipe
// that R1..R8 measurements show is the actual binding resource).
__device__ __forceinline__ __half2 tanh_h2(__half2 x) {
    __half2 y;
    asm("tanh.approx.f16x2 %0, %1;"
        : "=r"(*(uint32_t*)&y) : "r"(*(const uint32_t*)&x));
    return y;
}
__device__ __forceinline__ float tanh_acc(float a) {
    float e = ex2f(a * (2.0f * LOG2E));
    return fmaf(-2.0f, rcpf(e + 1.0f), 1.0f);
}
__device__ __forceinline__ float sigmoid_fast(float a) {
    float e = ex2f(-a * LOG2E);
    return rcpf(1.0f + e);
}

// ---------------- init ------------------------------------------------------
__global__ void init_kernel() {
    int i = blockIdx.x * blockDim.x + threadIdx.x;
    if (i < Bv * Fv) g_WaS[i] = __float2half(0.0f);
    if (i < Bv * Uv) g_h[i] = 0.0f;
}

// ---------------- tensor-core GEMM: fp32 in (converted to fp16), fp32 acc --
#define BM 128
#define BN 128
#define BKg 16
#define PITCH 24

__device__ __forceinline__ void mma16816(float* d,
    uint32_t a0, uint32_t a1, uint32_t a2, uint32_t a3,
    uint32_t b0, uint32_t b1)
{
    asm volatile(
        "mma.sync.aligned.m16n8k16.row.col.f32.f16.f16.f32 "
        "{%0,%1,%2,%3}, {%4,%5,%6,%7}, {%8,%9}, {%0,%1,%2,%3};"
        : "+f"(d[0]), "+f"(d[1]), "+f"(d[2]), "+f"(d[3])
        : "r"(a0), "r"(a1), "r"(a2), "r"(a3), "r"(b0), "r"(b1));
}

__global__ __launch_bounds__(256)
void gemm_mma(const float* __restrict__ A, int lda,
              const float* __restrict__ Bm, int ldb,
              __half* __restrict__ Cm, int ldc, int Ncols,
              const float* __restrict__ bias1,
              const float* __restrict__ bias2)
{
    __shared__ __align__(16) __half As[BM * PITCH];   // [m][k]
    __shared__ __align__(16) __half Bs[BN * PITCH];   // [n][k]

    int tid = threadIdx.x, lane = tid & 31, wid = tid >> 5;
    int warp_m = wid & 3, warp_n = wid >> 2;
    int bm = blockIdx.y * BM, bn = blockIdx.x * BN;
    int g = lane >> 2, tg = lane & 3;

    int a_row[2], a_kq[2], b_n[2], b_kq[2];
#pragma unroll
    for (int i = 0; i < 2; i++) {
        int fa = tid + 256 * i;
        a_row[i] = fa >> 2; a_kq[i] = fa & 3;
        b_n[i] = fa & 127;  b_kq[i] = fa >> 7;
    }

    float4 pa[2];
    float  pb[2][4];
#pragma unroll
    for (int i = 0; i < 2; i++) {
        pa[i] = *(const float4*)&A[(size_t)(bm + a_row[i]) * lda + a_kq[i] * 4];
        int col = bn + b_n[i];
        bool ok = col < Ncols;
#pragma unroll
        for (int j = 0; j < 4; j++)
            pb[i][j] = ok ? Bm[(size_t)(b_kq[i] * 4 + j) * ldb + col] : 0.0f;
    }

    float acc[2][8][4];
#pragma unroll
    for (int t = 0; t < 2; t++)
#pragma unroll
        for (int j = 0; j < 8; j++)
#pragma unroll
            for (int q = 0; q < 4; q++) acc[t][j][q] = 0.0f;

    const int KT = Fv / BKg;
    for (int kt = 0; kt < KT; kt++) {
        __syncthreads();
#pragma unroll
        for (int i = 0; i < 2; i++) {
            __half2 h0 = __floats2half2_rn(pa[i].x, pa[i].y);
            __half2 h1 = __floats2half2_rn(pa[i].z, pa[i].w);
            *(__half2*)&As[a_row[i] * PITCH + a_kq[i] * 4]     = h0;
            *(__half2*)&As[a_row[i] * PITCH + a_kq[i] * 4 + 2] = h1;
            __half2 g0 = __floats2half2_rn(pb[i][0], pb[i][1]);
            __half2 g1 = __floats2half2_rn(pb[i][2], pb[i][3]);
            *(__half2*)&Bs[b_n[i] * PITCH + b_kq[i] * 4]     = g0;
            *(__half2*)&Bs[b_n[i] * PITCH + b_kq[i] * 4 + 2] = g1;
        }
        if (kt + 1 < KT) {
            int k0 = (kt + 1) * BKg;
#pragma unroll
            for (int i = 0; i < 2; i++) {
                pa[i] = *(const float4*)&A[(size_t)(bm + a_row[i]) * lda + k0 + a_kq[i] * 4];
                int col = bn + b_n[i];
                bool ok = col < Ncols;
#pragma unroll
                for (int j = 0; j < 4; j++)
                    pb[i][j] = ok ? Bm[(size_t)(k0 + b_kq[i] * 4 + j) * ldb + col] : 0.0f;
            }
        }
        __syncthreads();

        uint32_t af[2][4];
#pragma unroll
        for (int t = 0; t < 2; t++) {
            int m = warp_m * 32 + t * 16 + g;
            af[t][0] = *(const uint32_t*)&As[m * PITCH + tg * 2];
            af[t][1] = *(const uint32_t*)&As[(m + 8) * PITCH + tg * 2];
            af[t][2] = *(const uint32_t*)&As[m * PITCH + tg * 2 + 8];
            af[t][3] = *(const uint32_t*)&As[(m + 8) * PITCH + tg * 2 + 8];
        }
#pragma unroll
        for (int j = 0; j < 8; j++) {
            int n = warp_n * 64 + j * 8 + g;
            uint32_t b0 = *(const uint32_t*)&Bs[n * PITCH + tg * 2];
            uint32_t b1 = *(const uint32_t*)&Bs[n * PITCH + tg * 2 + 8];
#pragma unroll
            for (int t = 0; t < 2; t++)
                mma16816(acc[t][j], af[t][0], af[t][1], af[t][2], af[t][3], b0, b1);
        }
    }

#pragma unroll
    for (int t = 0; t < 2; t++) {
        int row = bm + warp_m * 32 + t * 16 + g;
#pragma unroll
        for (int j = 0; j < 8; j++) {
            int col = bn + warp_n * 64 + j * 8 + tg * 2;
            if (col < Ncols) {
                float bb0 = 0.f, bb1 = 0.f;
                if (bias1) {
                    bb0 = bias1[col] + bias2[col];
                    bb1 = bias1[col + 1] + bias2[col + 1];
                }
                __half2 lo = __floats2half2_rn(acc[t][j][0] + bb0, acc[t][j][1] + bb1);
                __half2 hi = __floats2half2_rn(acc[t][j][2] + bb0, acc[t][j][3] + bb1);
                *(__half2*)&Cm[(size_t)row * ldc + col]       = lo;
                *(__half2*)&Cm[(size_t)(row + 8) * ldc + col] = hi;
            }
        }
    }
}

// ---------------- per-step score kernel ------------------------------------
// Block = (b, chunk of 30 t's). WaS[b] + Va staged in smem once per block;
// warp walks rows with next-row prefetch. tanh done 2-wide in fp16
// (tanh.approx.f16x2) — halves the MUFU.TANH count that was the measured
// binding pipe across R1..R8. Accumulation stays fp32.
__global__ __launch_bounds__(256)
void score_kernel(const float* __restrict__ Va)
{
    __shared__ float  sVa[Fv];      // 4 KB
    __shared__ __half sW[Fv];       // 2 KB

    int b = blockIdx.y;
    int t0 = blockIdx.x * TCH;
    int tid = threadIdx.x, warp = tid >> 5, lane = tid & 31;

    ((float4*)sVa)[tid] = ((const float4*)Va)[tid];            // 256 x 16B
    if (tid < 128)
        ((uint4*)sW)[tid] = ((const uint4*)(g_WaS + (size_t)b * Fv))[tid];
    __syncthreads();

    int tEnd = t0 + TCH; if (tEnd > Tv) tEnd = Tv;
    int t = t0 + warp;
    if (t >= tEnd) return;

    const uint4* Cb = (const uint4*)(g_C + (size_t)b * Tv * Fv);  // 128 chunks/row

    uint4 cur[4];
#pragma unroll
    for (int i = 0; i < 4; i++)
        cur[i] = __ldg(Cb + (size_t)t * 128 + i * 32 + lane);

    while (t < tEnd) {
        int tn = t + 8;
        int tl = (tn < tEnd) ? tn : t;        // clamp: prefetch valid memory
        uint4 nxt[4];
#pragma unroll
        for (int i = 0; i < 4; i++)
            nxt[i] = __ldg(Cb + (size_t)tl * 128 + i * 32 + lane);

        float a0 = 0.f, a1 = 0.f, a2 = 0.f, a3 = 0.f;
#pragma unroll
        for (int i = 0; i < 4; i++) {
            int idx = i * 32 + lane;
            uint4 w = *(const uint4*)&sW[idx * 8];
            float4 v0 = *(const float4*)&sVa[idx * 8];
            float4 v1 = *(const float4*)&sVa[idx * 8 + 4];
            const __half2* ch = (const __half2*)&cur[i];
            const __half2* wh = (const __half2*)&w;

            float2 t0f = __half22float2(tanh_h2(__hadd2(ch[0], wh[0])));
            float2 t1f = __half22float2(tanh_h2(__hadd2(ch[1], wh[1])));
            float2 t2f = __half22float2(tanh_h2(__hadd2(ch[2], wh[2])));
            float2 t3f = __half22float2(tanh_h2(__hadd2(ch[3], wh[3])));

            a0 = fmaf(t0f.x, v0.x, a0);
            a1 = fmaf(t0f.y, v0.y, a1);
            a2 = fmaf(t1f.x, v0.z, a2);
            a3 = fmaf(t1f.y, v0.w, a3);
            a0 = fmaf(t2f.x, v1.x, a0);
            a1 = fmaf(t2f.y, v1.y, a1);
            a2 = fmaf(t3f.x, v1.z, a2);
            a3 = fmaf(t3f.y, v1.w, a3);
        }
        float sum = (a0 + a1) + (a2 + a3);
#pragma unroll
        for (int off = 16; off > 0; off >>= 1)
            sum += __shfl_xor_sync(0xffffffffu, sum, off);
        if (lane == 0) g_scores[b * Tv + t] = sum;

#pragma unroll
        for (int i = 0; i < 4; i++) cur[i] = nxt[i];
        t = tn;
    }
}

// ---------------- per-step softmax + GRU + next WaS (1 block per batch b) --
__global__ __launch_bounds__(256)
void att_gru_kernel(const float* __restrict__ Wa,
                    const float* __restrict__ grk,
                    const float* __restrict__ gb,
                    float* __restrict__ out, int tstep)
{
    int b = blockIdx.x, tid = threadIdx.x;

    __shared__ float sa[Tv];
    __shared__ float red[256];
    __shared__ float spart[3 * G3];
    __shared__ float sxz[G3], shz[G3];
    __shared__ float sh[Uv], shnew[Uv];

    if (tid < Uv) sh[tid] = g_h[b * Uv + tid];

    // ---- softmax over T=150 scores ----
    float v = (tid < Tv) ? g_scores[b * Tv + tid] : -1e30f;
    red[tid] = v;
    __syncthreads();
#pragma unroll
    for (int s = 128; s > 0; s >>= 1) {
        if (tid < s) red[tid] = fmaxf(red[tid], red[tid + s]);
        __syncthreads();
    }
    float mx = red[0];
    __syncthreads();
    float e = 0.0f;
    if (tid < Tv) e = ex2f((v - mx) * LOG2E);
    red[tid] = e;
    __syncthreads();
#pragma unroll
    for (int s = 128; s > 0; s >>= 1) {
        if (tid < s) red[tid] += red[tid + s];
        __syncthreads();
    }
    float inv = rcpf(red[0]);
    if (tid < Tv) sa[tid] = e * inv;
    __syncthreads();

    // ---- xz[j] = bias0[j] + sum_t a[t] * XG[b,t,j] ----
    int part = tid / G3;        // 0..2 used; tid>=252 idle
    int j = tid - part * G3;
    if (part < 3) {
        float acc = 0.0f;
        const __half* XGb = g_XG + (size_t)b * Tv * G3 + j;
        for (int t = part; t < Tv; t += 3)
            acc = fmaf(sa[t], __half2float(XGb[t * G3]), acc);
        spart[part * G3 + j] = acc;
    }
    __syncthreads();

    if (tid < G3) {
        float xz = gb[tid] + spart[tid] + spart[G3 + tid] + spart[2 * G3 + tid];
        float hzv = gb[G3 + tid];
#pragma unroll
        for (int u = 0; u < Uv; u++)
            hzv = fmaf(sh[u], grk[u * G3 + tid], hzv);
        sxz[tid] = xz;
        shz[tid] = hzv;
    }
    __syncthreads();

    // ---- GRU gates (reset_after=True) ----
    if (tid < Uv) {
        float z  = sigmoid_fast(sxz[tid]          + shz[tid]);
        float r  = sigmoid_fast(sxz[Uv + tid]     + shz[Uv + tid]);
        float hh = tanh_acc    (sxz[2 * Uv + tid] + r * shz[2 * Uv + tid]);
        float hn = hh + z * (sh[tid] - hh);
        g_h[b * Uv + tid] = hn;
        out[((size_t)b * Tv + tstep) * Uv + tid] = hn;
        shnew[tid] = hn;
    }
    __syncthreads();

    // ---- WaS for next step: h_new @ Wa (stored fp16) ----
    float4 w = make_float4(0.f, 0.f, 0.f, 0.f);
    const float4* Wa4 = (const float4*)Wa;
#pragma unroll
    for (int u = 0; u < Uv; u++) {
        float hv = shnew[u];
        float4 wv = Wa4[u * (Fv / 4) + tid];
        w.x = fmaf(hv, wv.x, w.x);
        w.y = fmaf(hv, wv.y, w.y);
        w.z = fmaf(hv, wv.z, w.z);
        w.w = fmaf(hv, wv.w, w.w);
    }
    __half2 p0 = __floats2half2_rn(w.x, w.y);
    __half2 p1 = __floats2half2_rn(w.z, w.w);
    uint2 pk;
    pk.x = *(uint32_t*)&p0;
    pk.y = *(uint32_t*)&p1;
    ((uint2*)g_WaS)[b * (Fv / 4) + tid] = pk;
}

// ---------------- launch -----------------------------------------------------
extern "C" void kernel_launch(void* const* d_in, const int* in_sizes, int n_in,
                              void* d_out, int out_size)
{
    const float* x   = (const float*)d_in[0];  // (B,T,F)
    const float* Wa  = (const float*)d_in[1];  // (U,F)
    const float* Ua  = (const float*)d_in[2];  // (F,F)
    const float* Va  = (const float*)d_in[3];  // (F,1)
    const float* Ba1 = (const float*)d_in[4];  // (1,F)
    const float* Ba2 = (const float*)d_in[5];  // (1,F)
    // d_in[6] = Ba3 : softmax-invariant, unused
    const float* gk  = (const float*)d_in[7];  // (F,3U)
    const float* grk = (const float*)d_in[8];  // (U,3U)
    const float* gb  = (const float*)d_in[9];  // (2,3U)
    float* out = (float*)d_out;                // (B,T,U)

    init_kernel<<<(Bv * Fv + 255) / 256, 256>>>();

    __half* Cm;  cudaGetSymbolAddress((void**)&Cm, g_C);
    __half* XGm; cudaGetSymbolAddress((void**)&XGm, g_XG);

    // C = x @ Ua + Ba1 + Ba2  : M=38400, N=1024, K=1024  (fp16 out, HMMA)
    gemm_mma<<<dim3(Fv / BN, (Bv * Tv) / BM), 256>>>(
        x, Fv, Ua, Fv, Cm, Fv, Fv, Ba1, Ba2);
    // XG = x @ gru_kernel     : M=38400, N=84, K=1024    (fp16 out, HMMA)
    gemm_mma<<<dim3(1, (Bv * Tv) / BM), 256>>>(
        x, Fv, gk, G3, XGm, G3, G3, nullptr, nullptr);

    dim3 sgrid((Tv + TCH - 1) / TCH, Bv);   // (5, 256)
    for (int t = 0; t < Tv; t++) {
        score_kernel<<<sgrid, 256>>>(Va);
        att_gru_kernel<<<Bv, 256>>>(Wa, grk, gb, out, t);
    }
}